// round 6
// baseline (speedup 1.0000x reference)
#include <cuda_runtime.h>

#define FULLMASK 0xffffffffu

// Problem dims (fixed by the dataset)
#define Bb 16
#define Ss 256
#define Nn 16
#define Dd 6
#define Hh 16
#define CHAINS (Bb * Nn)   // 256
#define HW (Hh * 32)       // 512

// Per-(row) projection partials, layout [row][d*16 + head] = 25 MB
__device__ float g_part[(size_t)CHAINS * Ss * 96];

// ---------------------------------------------------------------------------
// Phase 1: rotor recurrence + fused output projection.
// 8 lanes per head (4 blades/lane), 4 heads/warp, TWO independent chains per
// warp (c and c+128, same head-quad -> shared weights). 512 warps launched as
// 128 blocks x 128 threads = 1 warp/SMSP, 2-way chain ILP hides all latency.
//
// Math: delta normalization elided (GP bilinear, absorbed by outer norm);
// psi_t = normalize(GP(u_t, psi_{t-1})) computed EXACTLY each step.
// ---------------------------------------------------------------------------
__global__ void __launch_bounds__(128) rotor_rnn_kernel(
    const float* __restrict__ x,      // [B,S,N,D]
    const float* __restrict__ W_in,   // [D, H*32]
    const float* __restrict__ b_in,   // [H*32]
    const float* __restrict__ W_out)  // [H*32, D]
{
    const int gw   = (blockIdx.x * blockDim.x + threadIdx.x) >> 5;  // 0..511
    const int lane = threadIdx.x & 31;
    const int hq = gw & 3;            // head quad
    const int cp = gw >> 2;           // chain pair 0..127
    const int cA = cp;
    const int cB = cp + 128;
    const int w  = lane >> 3;         // head within quad
    const int g  = lane & 7;          // blade group
    const int h  = hq * 4 + w;
    const int col0 = h * 32 + g * 4;

    // Shared persistent weights (identical for both chains)
    float wi[4][Dd];
    float bi[4];
#pragma unroll
    for (int r = 0; r < 4; ++r) {
#pragma unroll
        for (int d = 0; d < Dd; ++d) wi[r][d] = __ldg(W_in + d * HW + col0 + r);
        bi[r] = __ldg(b_in + col0 + r);
    }
    float wo[4][Dd];
#pragma unroll
    for (int r = 0; r < 4; ++r)
#pragma unroll
        for (int d = 0; d < Dd; ++d) wo[r][d] = __ldg(W_out + (col0 + r) * Dd + d);

    // Per-(lane, mask) sigma sign: sigma = G0*(m1^m2) ^ G1*m2, G = g^m
    unsigned sm8[8];
#pragma unroll
    for (int m = 0; m < 8; ++m) {
        unsigned G  = (unsigned)(g ^ m);
        unsigned m1 = (m >> 1) & 1u, m2 = (m >> 2) & 1u;
        unsigned sgn = ((G & 1u) & (m1 ^ m2)) ^ (((G >> 1) & 1u) & m2);
        sm8[m] = sgn << 31;
    }

    // psi state per chain (init = identity rotor)
    float wA0 = (g == 0) ? 1.0f : 0.0f, wA1 = 0.f, wA2 = 0.f, wA3 = 0.f;
    float wB0 = wA0, wB1 = 0.f, wB2 = 0.f, wB3 = 0.f;

    const float* xpA = x + ((size_t)((cA >> 4) * Ss) * Nn + (cA & 15)) * Dd;
    const float* xpB = x + ((size_t)((cB >> 4) * Ss) * Nn + (cB & 15)) * Dd;
    // partial store: [row][d*16 + h], row = c*256 + t; lane g stores d=g (g<6)
    float* pwA = g_part + ((size_t)cA * Ss) * 96 + g * 16 + h;
    float* pwB = g_part + ((size_t)cB * Ss) * 96 + g * 16 + h;

    float cxA[Dd], cxB[Dd];
#pragma unroll
    for (int d = 0; d < Dd; ++d) { cxA[d] = __ldg(xpA + d); cxB[d] = __ldg(xpB + d); }

    for (int t = 0; t < Ss; ++t) {
        // prefetch next x for both chains (warp-uniform broadcasts)
        const float* xnA = xpA + Nn * Dd;
        const float* xnB = xpB + Nn * Dd;
        const bool more = (t + 1 < Ss);
        float nxA[Dd], nxB[Dd];
#pragma unroll
        for (int d = 0; d < Dd; ++d) {
            nxA[d] = more ? __ldg(xnA + d) : 0.0f;
            nxB[d] = more ? __ldg(xnB + d) : 0.0f;
        }

        // u = x @ W_in + b_in ; +1 on blade 0 (delta-norm elided)
        float dA0 = bi[0], dA1 = bi[1], dA2 = bi[2], dA3 = bi[3];
        float dB0 = bi[0], dB1 = bi[1], dB2 = bi[2], dB3 = bi[3];
#pragma unroll
        for (int d = 0; d < Dd; ++d) {
            dA0 = fmaf(wi[0][d], cxA[d], dA0);
            dA1 = fmaf(wi[1][d], cxA[d], dA1);
            dA2 = fmaf(wi[2][d], cxA[d], dA2);
            dA3 = fmaf(wi[3][d], cxA[d], dA3);
            dB0 = fmaf(wi[0][d], cxB[d], dB0);
            dB1 = fmaf(wi[1][d], cxB[d], dB1);
            dB2 = fmaf(wi[2][d], cxB[d], dB2);
            dB3 = fmaf(wi[3][d], cxB[d], dB3);
        }
        if (g == 0) { dA0 += 1.0f; dB0 += 1.0f; }

        // geometric product, both chains interleaved
        float pAa0, pAa1, pAa2, pAa3, pAb0 = 0.f, pAb1 = 0.f, pAb2 = 0.f, pAb3 = 0.f;
        float pBa0, pBa1, pBa2, pBa3, pBb0 = 0.f, pBb1 = 0.f, pBb2 = 0.f, pBb3 = 0.f;

        // ---- m = 0: ps local, sigma = 0, P = 0 ----
        {
            float aA0 = __shfl_sync(FULLMASK, dA0, 0, 8);
            float aA1 = __shfl_sync(FULLMASK, dA1, 0, 8);
            float aA2 = __shfl_sync(FULLMASK, dA2, 0, 8);
            float aA3 = __shfl_sync(FULLMASK, dA3, 0, 8);
            float aB0 = __shfl_sync(FULLMASK, dB0, 0, 8);
            float aB1 = __shfl_sync(FULLMASK, dB1, 0, 8);
            float aB2 = __shfl_sync(FULLMASK, dB2, 0, 8);
            float aB3 = __shfl_sync(FULLMASK, dB3, 0, 8);

            pAa0 = aA0 * wA0; pAa1 = aA1 * wA0; pAa2 = aA2 * wA0; pAa3 = aA3 * wA0;
            pBa0 = aB0 * wB0; pBa1 = aB1 * wB0; pBa2 = aB2 * wB0; pBa3 = aB3 * wB0;
            pAa0 = fmaf( aA1, wA1, pAa0); pAa1 = fmaf( aA0, wA1, pAa1);
            pAa2 = fmaf(-aA3, wA1, pAa2); pAa3 = fmaf(-aA2, wA1, pAa3);
            pBa0 = fmaf( aB1, wB1, pBa0); pBa1 = fmaf( aB0, wB1, pBa1);
            pBa2 = fmaf(-aB3, wB1, pBa2); pBa3 = fmaf(-aB2, wB1, pBa3);
            pAa0 = fmaf( aA2, wA2, pAa0); pAa1 = fmaf( aA3, wA2, pAa1);
            pAa2 = fmaf( aA0, wA2, pAa2); pAa3 = fmaf( aA1, wA2, pAa3);
            pBa0 = fmaf( aB2, wB2, pBa0); pBa1 = fmaf( aB3, wB2, pBa1);
            pBa2 = fmaf( aB0, wB2, pBa2); pBa3 = fmaf( aB1, wB2, pBa3);
            pAa0 = fmaf(-aA3, wA3, pAa0); pAa1 = fmaf(-aA2, wA3, pAa1);
            pAa2 = fmaf( aA1, wA3, pAa2); pAa3 = fmaf( aA0, wA3, pAa3);
            pBa0 = fmaf(-aB3, wB3, pBa0); pBa1 = fmaf(-aB2, wB3, pBa1);
            pBa2 = fmaf( aB1, wB3, pBa2); pBa3 = fmaf( aB0, wB3, pBa3);
        }

        // ---- m = 1..7 ----
#pragma unroll
        for (int m = 1; m < 8; ++m) {
            float mA0 = __shfl_xor_sync(FULLMASK, wA0, m);
            float mA1 = __shfl_xor_sync(FULLMASK, wA1, m);
            float mA2 = __shfl_xor_sync(FULLMASK, wA2, m);
            float mA3 = __shfl_xor_sync(FULLMASK, wA3, m);
            float mB0 = __shfl_xor_sync(FULLMASK, wB0, m);
            float mB1 = __shfl_xor_sync(FULLMASK, wB1, m);
            float mB2 = __shfl_xor_sync(FULLMASK, wB2, m);
            float mB3 = __shfl_xor_sync(FULLMASK, wB3, m);
            const unsigned sg = sm8[m];
            float aA0 = __uint_as_float(__float_as_uint(__shfl_sync(FULLMASK, dA0, m, 8)) ^ sg);
            float aA1 = __uint_as_float(__float_as_uint(__shfl_sync(FULLMASK, dA1, m, 8)) ^ sg);
            float aA2 = __uint_as_float(__float_as_uint(__shfl_sync(FULLMASK, dA2, m, 8)) ^ sg);
            float aA3 = __uint_as_float(__float_as_uint(__shfl_sync(FULLMASK, dA3, m, 8)) ^ sg);
            float aB0 = __uint_as_float(__float_as_uint(__shfl_sync(FULLMASK, dB0, m, 8)) ^ sg);
            float aB1 = __uint_as_float(__float_as_uint(__shfl_sync(FULLMASK, dB1, m, 8)) ^ sg);
            float aB2 = __uint_as_float(__float_as_uint(__shfl_sync(FULLMASK, dB2, m, 8)) ^ sg);
            float aB3 = __uint_as_float(__float_as_uint(__shfl_sync(FULLMASK, dB3, m, 8)) ^ sg);

            const unsigned P = ((m) ^ (m >> 1) ^ (m >> 2)) & 1u;
            float& qA0 = (m & 1) ? pAb0 : pAa0;
            float& qA1 = (m & 1) ? pAb1 : pAa1;
            float& qA2 = (m & 1) ? pAb2 : pAa2;
            float& qA3 = (m & 1) ? pAb3 : pAa3;
            float& qB0 = (m & 1) ? pBb0 : pBa0;
            float& qB1 = (m & 1) ? pBb1 : pBa1;
            float& qB2 = (m & 1) ? pBb2 : pBa2;
            float& qB3 = (m & 1) ? pBb3 : pBa3;

            // jr = 0: +
            qA0 = fmaf(aA0, mA0, qA0); qA1 = fmaf(aA1, mA0, qA1);
            qA2 = fmaf(aA2, mA0, qA2); qA3 = fmaf(aA3, mA0, qA3);
            qB0 = fmaf(aB0, mB0, qB0); qB1 = fmaf(aB1, mB0, qB1);
            qB2 = fmaf(aB2, mB0, qB2); qB3 = fmaf(aB3, mB0, qB3);
            // jr = 1: neg = kr1 ^ P
            if (P == 0) {
                qA0 = fmaf( aA1, mA1, qA0); qA1 = fmaf( aA0, mA1, qA1);
                qA2 = fmaf(-aA3, mA1, qA2); qA3 = fmaf(-aA2, mA1, qA3);
                qB0 = fmaf( aB1, mB1, qB0); qB1 = fmaf( aB0, mB1, qB1);
                qB2 = fmaf(-aB3, mB1, qB2); qB3 = fmaf(-aB2, mB1, qB3);
            } else {
                qA0 = fmaf(-aA1, mA1, qA0); qA1 = fmaf(-aA0, mA1, qA1);
                qA2 = fmaf( aA3, mA1, qA2); qA3 = fmaf( aA2, mA1, qA3);
                qB0 = fmaf(-aB1, mB1, qB0); qB1 = fmaf(-aB0, mB1, qB1);
                qB2 = fmaf( aB3, mB1, qB2); qB3 = fmaf( aB2, mB1, qB3);
            }
            // jr = 2: neg = P
            if (P == 0) {
                qA0 = fmaf( aA2, mA2, qA0); qA1 = fmaf( aA3, mA2, qA1);
                qA2 = fmaf( aA0, mA2, qA2); qA3 = fmaf( aA1, mA2, qA3);
                qB0 = fmaf( aB2, mB2, qB0); qB1 = fmaf( aB3, mB2, qB1);
                qB2 = fmaf( aB0, mB2, qB2); qB3 = fmaf( aB1, mB2, qB3);
            } else {
                qA0 = fmaf(-aA2, mA2, qA0); qA1 = fmaf(-aA3, mA2, qA1);
                qA2 = fmaf(-aA0, mA2, qA2); qA3 = fmaf(-aA1, mA2, qA3);
                qB0 = fmaf(-aB2, mB2, qB0); qB1 = fmaf(-aB3, mB2, qB1);
                qB2 = fmaf(-aB0, mB2, qB2); qB3 = fmaf(-aB1, mB2, qB3);
            }
            // jr = 3: neg = kr1^1 (P-independent)
            qA0 = fmaf(-aA3, mA3, qA0); qA1 = fmaf(-aA2, mA3, qA1);
            qA2 = fmaf( aA1, mA3, qA2); qA3 = fmaf( aA0, mA3, qA3);
            qB0 = fmaf(-aB3, mB3, qB0); qB1 = fmaf(-aB2, mB3, qB1);
            qB2 = fmaf( aB1, mB3, qB2); qB3 = fmaf( aB0, mB3, qB3);
        }
        float nA0 = pAa0 + pAb0, nA1 = pAa1 + pAb1, nA2 = pAa2 + pAb2, nA3 = pAa3 + pAb3;
        float nB0 = pBa0 + pBb0, nB1 = pBa1 + pBb1, nB2 = pBa2 + pBb2, nB3 = pBa3 + pBb3;

        // exact normalization, both chains (interleaved -> latency hidden)
        float sA = nA0 * nA0 + nA1 * nA1;
        float sB = nB0 * nB0 + nB1 * nB1;
        sA = fmaf(nA2, nA2, sA); sA = fmaf(nA3, nA3, sA);
        sB = fmaf(nB2, nB2, sB); sB = fmaf(nB3, nB3, sB);
        sA += __shfl_xor_sync(FULLMASK, sA, 1);
        sB += __shfl_xor_sync(FULLMASK, sB, 1);
        sA += __shfl_xor_sync(FULLMASK, sA, 2);
        sB += __shfl_xor_sync(FULLMASK, sB, 2);
        sA += __shfl_xor_sync(FULLMASK, sA, 4);
        sB += __shfl_xor_sync(FULLMASK, sB, 4);
        sA += 1e-12f; sB += 1e-12f;
        float rA = rsqrtf(sA), rB = rsqrtf(sB);
        rA = rA * (1.5f - 0.5f * sA * rA * rA);
        rB = rB * (1.5f - 0.5f * sB * rB * rB);
        wA0 = nA0 * rA; wA1 = nA1 * rA; wA2 = nA2 * rA; wA3 = nA3 * rA;
        wB0 = nB0 * rB; wB1 = nB1 * rB; wB2 = nB2 * rB; wB3 = nB3 * rB;

        // projection partials, both chains
        float pA0, pA1, pA2, pA3, pA4, pA5;
        float pB0, pB1, pB2, pB3, pB4, pB5;
        pA0 = wA0 * wo[0][0]; pA1 = wA0 * wo[0][1]; pA2 = wA0 * wo[0][2];
        pA3 = wA0 * wo[0][3]; pA4 = wA0 * wo[0][4]; pA5 = wA0 * wo[0][5];
        pB0 = wB0 * wo[0][0]; pB1 = wB0 * wo[0][1]; pB2 = wB0 * wo[0][2];
        pB3 = wB0 * wo[0][3]; pB4 = wB0 * wo[0][4]; pB5 = wB0 * wo[0][5];
#pragma unroll
        for (int r = 1; r < 4; ++r) {
            const float sa = (r == 1) ? wA1 : (r == 2) ? wA2 : wA3;
            const float sb = (r == 1) ? wB1 : (r == 2) ? wB2 : wB3;
            pA0 = fmaf(sa, wo[r][0], pA0); pA1 = fmaf(sa, wo[r][1], pA1);
            pA2 = fmaf(sa, wo[r][2], pA2); pA3 = fmaf(sa, wo[r][3], pA3);
            pA4 = fmaf(sa, wo[r][4], pA4); pA5 = fmaf(sa, wo[r][5], pA5);
            pB0 = fmaf(sb, wo[r][0], pB0); pB1 = fmaf(sb, wo[r][1], pB1);
            pB2 = fmaf(sb, wo[r][2], pB2); pB3 = fmaf(sb, wo[r][3], pB3);
            pB4 = fmaf(sb, wo[r][4], pB4); pB5 = fmaf(sb, wo[r][5], pB5);
        }
#pragma unroll
        for (int o = 1; o < 8; o <<= 1) {
            pA0 += __shfl_xor_sync(FULLMASK, pA0, o);
            pB0 += __shfl_xor_sync(FULLMASK, pB0, o);
            pA1 += __shfl_xor_sync(FULLMASK, pA1, o);
            pB1 += __shfl_xor_sync(FULLMASK, pB1, o);
            pA2 += __shfl_xor_sync(FULLMASK, pA2, o);
            pB2 += __shfl_xor_sync(FULLMASK, pB2, o);
            pA3 += __shfl_xor_sync(FULLMASK, pA3, o);
            pB3 += __shfl_xor_sync(FULLMASK, pB3, o);
            pA4 += __shfl_xor_sync(FULLMASK, pA4, o);
            pB4 += __shfl_xor_sync(FULLMASK, pB4, o);
            pA5 += __shfl_xor_sync(FULLMASK, pA5, o);
            pB5 += __shfl_xor_sync(FULLMASK, pB5, o);
        }
        float pvA = (g == 0) ? pA0 : (g == 1) ? pA1 : (g == 2) ? pA2
                  : (g == 3) ? pA3 : (g == 4) ? pA4 : pA5;
        float pvB = (g == 0) ? pB0 : (g == 1) ? pB1 : (g == 2) ? pB2
                  : (g == 3) ? pB3 : (g == 4) ? pB4 : pB5;
        if (g < 6) { *pwA = pvA; *pwB = pvB; }
        pwA += 96; pwB += 96;

        xpA = xnA; xpB = xnB;
#pragma unroll
        for (int d = 0; d < Dd; ++d) { cxA[d] = nxA[d]; cxB[d] = nxB[d]; }
    }
}

// ---------------------------------------------------------------------------
// Phase 2: combine — y[row,d] = x[row,d] + b_out[d] + sum_{16 heads} part
// Partials are contiguous per (row,d): 4x LDG.128.
// ---------------------------------------------------------------------------
__global__ void __launch_bounds__(256) combine_kernel(
    const float* __restrict__ x,
    const float* __restrict__ b_out,
    float* __restrict__ y)
{
    const int e   = blockIdx.x * blockDim.x + threadIdx.x;  // 0..393215
    const int row = e / 6;              // chain*256 + t
    const int d   = e - row * 6;

    const float4* pp = (const float4*)(g_part + (size_t)row * 96 + d * 16);
    float4 v0 = __ldg(pp + 0);
    float4 v1 = __ldg(pp + 1);
    float4 v2 = __ldg(pp + 2);
    float4 v3 = __ldg(pp + 3);
    float acc = __ldg(b_out + d)
              + ((v0.x + v0.y) + (v0.z + v0.w))
              + ((v1.x + v1.y) + (v1.z + v1.w))
              + ((v2.x + v2.y) + (v2.z + v2.w))
              + ((v3.x + v3.y) + (v3.z + v3.w));

    const int c = row >> 8;
    const int t = row & (Ss - 1);
    const int b = c >> 4;
    const int n = c & (Nn - 1);
    const size_t off = (((size_t)b * Ss + t) * Nn + n) * Dd + d;
    y[off] = __ldg(x + off) + acc;
}

extern "C" void kernel_launch(void* const* d_in, const int* in_sizes, int n_in,
                              void* d_out, int out_size) {
    const float* x     = (const float*)d_in[0];
    const float* W_in  = (const float*)d_in[1];
    const float* b_in  = (const float*)d_in[2];
    const float* W_out = (const float*)d_in[3];
    const float* b_out = (const float*)d_in[4];
    float* y = (float*)d_out;

    // Phase 1: 512 warps, 1/SMSP, 2 chains per warp
    rotor_rnn_kernel<<<128, 128>>>(x, W_in, b_in, W_out);
    // Phase 2: combine (65536 rows x 6)
    combine_kernel<<<1536, 256>>>(x, b_out, y);
}

// round 7
// speedup vs baseline: 1.2008x; 1.2008x over previous
#include <cuda_runtime.h>

#define FULLMASK 0xffffffffu

// Problem dims (fixed by the dataset)
#define Bb 16
#define Ss 256
#define Nn 16
#define Dd 6
#define Hh 16
#define CHAINS (Bb * Nn)   // 256
#define HW (Hh * 32)       // 512

// Per-(row) projection partials, layout [row][d*16 + head] = 25 MB
__device__ float g_part[(size_t)CHAINS * Ss * 96];

// ---------------------------------------------------------------------------
// Phase 1: rotor recurrence + fused output projection (R5 structure).
// 8 lanes per head (4 blades/lane), 4 heads/warp, 1 chain/warp, 1024 warps.
//
// Recurrence carries the UNNORMALIZED product w_t:
//   w_t = GP(u_t * rn_{t-2}, w_{t-1})          (norm OFF the critical path)
//   psi_t = w_t * rsqrt(|w_t|^2 + 1e-12)       (exact normalize for output)
//
// NEW: the GP cross-lane exchange goes through shared memory (2x STS.128 +
// 15x LDS.128 + 1 __syncwarp, double-buffered) instead of 60 shuffles.
// ---------------------------------------------------------------------------
__global__ void __launch_bounds__(256) rotor_rnn_kernel(
    const float* __restrict__ x,      // [B,S,N,D]
    const float* __restrict__ W_in,   // [D, H*32]
    const float* __restrict__ b_in,   // [H*32]
    const float* __restrict__ W_out)  // [H*32, D]
{
    // [buf][warp][0=w,1=dl][lane]  -> 16 KB
    __shared__ float4 sbuf[2][8][2][32];

    const int gw   = (blockIdx.x * blockDim.x + threadIdx.x) >> 5;  // 0..1023
    const int wid  = (threadIdx.x >> 5) & 7;
    const int lane = threadIdx.x & 31;
    const int c  = gw >> 2;           // chain 0..255
    const int hq = gw & 3;            // head quad within chain
    const int w  = lane >> 3;         // head within quad
    const int g  = lane & 7;          // blade group (blades g*4 .. g*4+3)
    const int h  = hq * 4 + w;
    const int b  = c >> 4;
    const int n  = c & (Nn - 1);
    const int col0 = h * 32 + g * 4;
    const int dlid = lane & 24;       // own head's lane base

    // W_in columns + bias for this lane's 4 blades
    float wi[4][Dd];
    float bi[4];
#pragma unroll
    for (int r = 0; r < 4; ++r) {
#pragma unroll
        for (int d = 0; d < Dd; ++d) wi[r][d] = __ldg(W_in + d * HW + col0 + r);
        bi[r] = __ldg(b_in + col0 + r);
    }
    // W_out rows for this lane's 4 blades
    float wo[4][Dd];
#pragma unroll
    for (int r = 0; r < 4; ++r)
#pragma unroll
        for (int d = 0; d < Dd; ++d) wo[r][d] = __ldg(W_out + (col0 + r) * Dd + d);

    // Per-(lane, mask) sigma sign: sigma = G0*(m1^m2) ^ G1*m2, G = g^m
    unsigned sm8[8];
#pragma unroll
    for (int m = 0; m < 8; ++m) {
        unsigned G  = (unsigned)(g ^ m);
        unsigned m1 = (m >> 1) & 1u, m2 = (m >> 2) & 1u;
        unsigned sgn = ((G & 1u) & (m1 ^ m2)) ^ (((G >> 1) & 1u) & m2);
        sm8[m] = sgn << 31;
    }

    // state: unnormalized carrier (init = identity rotor, |.|=1)
    float w0 = (g == 0) ? 1.0f : 0.0f, w1 = 0.f, w2 = 0.f, w3 = 0.f;
    float rnA = 1.0f;   // rn_{t-2}
    float rnB = 1.0f;   // rn_{t-1}

    const float* xp = x + ((size_t)(b * Ss) * Nn + n) * Dd;
    // partial store: [row][d*16 + h]; lane g stores d=g (g<6)
    float* pw = g_part + ((size_t)c * Ss) * 96 + g * 16 + h;

    float cx[Dd];
#pragma unroll
    for (int d = 0; d < Dd; ++d) cx[d] = __ldg(xp + d);

    for (int t = 0; t < Ss; ++t) {
        const int buf = t & 1;

        // prefetch next x (warp-uniform broadcast)
        const float* xn = xp + Nn * Dd;
        const bool more = (t + 1 < Ss);
        float nx[Dd];
#pragma unroll
        for (int d = 0; d < Dd; ++d) nx[d] = more ? __ldg(xn + d) : 0.0f;

        // u = x_t @ W_in + b_in ; +1 on blade 0 ; scaled by stale rn_{t-2}
        float dl0, dl1, dl2, dl3;
        {
            float a0 = bi[0], a1 = bi[1], a2 = bi[2], a3 = bi[3];
#pragma unroll
            for (int d = 0; d < Dd; ++d) {
                a0 = fmaf(wi[0][d], cx[d], a0);
                a1 = fmaf(wi[1][d], cx[d], a1);
                a2 = fmaf(wi[2][d], cx[d], a2);
                a3 = fmaf(wi[3][d], cx[d], a3);
            }
            if (g == 0) a0 += 1.0f;
            dl0 = a0 * rnA; dl1 = a1 * rnA; dl2 = a2 * rnA; dl3 = a3 * rnA;
        }

        // publish state + dl to smem (double-buffered; one syncwarp/step)
        sbuf[buf][wid][0][lane] = make_float4(w0, w1, w2, w3);
        sbuf[buf][wid][1][lane] = make_float4(dl0, dl1, dl2, dl3);
        __syncwarp();

        // geometric product (two accumulator banks for ILP)
        float pA0, pA1, pA2, pA3;
        float pB0 = 0.f, pB1 = 0.f, pB2 = 0.f, pB3 = 0.f;

        // ---- m = 0: w is LOCAL, dl broadcast from group 0, sigma=0, P=0 ----
        {
            const float4 dv = sbuf[buf][wid][1][dlid];
            const float a0 = dv.x, a1 = dv.y, a2 = dv.z, a3 = dv.w;
            pA0 = a0 * w0; pA1 = a1 * w0; pA2 = a2 * w0; pA3 = a3 * w0;
            pA0 = fmaf( a1, w1, pA0); pA1 = fmaf( a0, w1, pA1);
            pA2 = fmaf(-a3, w1, pA2); pA3 = fmaf(-a2, w1, pA3);
            pA0 = fmaf( a2, w2, pA0); pA1 = fmaf( a3, w2, pA1);
            pA2 = fmaf( a0, w2, pA2); pA3 = fmaf( a1, w2, pA3);
            pA0 = fmaf(-a3, w3, pA0); pA1 = fmaf(-a2, w3, pA1);
            pA2 = fmaf( a1, w3, pA2); pA3 = fmaf( a0, w3, pA3);
        }

        // ---- m = 1..7 ----
#pragma unroll
        for (int m = 1; m < 8; ++m) {
            const float4 wv = sbuf[buf][wid][0][lane ^ m];     // w[(g^m) group]
            const float4 dv = sbuf[buf][wid][1][dlid | m];     // dl[m group] (bcast)
            const unsigned sg = sm8[m];
            const float a0 = __uint_as_float(__float_as_uint(dv.x) ^ sg);
            const float a1 = __uint_as_float(__float_as_uint(dv.y) ^ sg);
            const float a2 = __uint_as_float(__float_as_uint(dv.z) ^ sg);
            const float a3 = __uint_as_float(__float_as_uint(dv.w) ^ sg);
            const float pm0 = wv.x, pm1 = wv.y, pm2 = wv.z, pm3 = wv.w;

            const unsigned P = ((m) ^ (m >> 1) ^ (m >> 2)) & 1u;
            float& q0 = (m & 1) ? pB0 : pA0;
            float& q1 = (m & 1) ? pB1 : pA1;
            float& q2 = (m & 1) ? pB2 : pA2;
            float& q3 = (m & 1) ? pB3 : pA3;

            // jr = 0: +
            q0 = fmaf(a0, pm0, q0);
            q1 = fmaf(a1, pm0, q1);
            q2 = fmaf(a2, pm0, q2);
            q3 = fmaf(a3, pm0, q3);
            // jr = 1: neg = kr1 ^ P
            if (P == 0) {
                q0 = fmaf( a1, pm1, q0); q1 = fmaf( a0, pm1, q1);
                q2 = fmaf(-a3, pm1, q2); q3 = fmaf(-a2, pm1, q3);
            } else {
                q0 = fmaf(-a1, pm1, q0); q1 = fmaf(-a0, pm1, q1);
                q2 = fmaf( a3, pm1, q2); q3 = fmaf( a2, pm1, q3);
            }
            // jr = 2: neg = P
            if (P == 0) {
                q0 = fmaf( a2, pm2, q0); q1 = fmaf( a3, pm2, q1);
                q2 = fmaf( a0, pm2, q2); q3 = fmaf( a1, pm2, q3);
            } else {
                q0 = fmaf(-a2, pm2, q0); q1 = fmaf(-a3, pm2, q1);
                q2 = fmaf(-a0, pm2, q2); q3 = fmaf(-a1, pm2, q3);
            }
            // jr = 3: neg = kr1^1 (P-independent)
            q0 = fmaf(-a3, pm3, q0);
            q1 = fmaf(-a2, pm3, q1);
            q2 = fmaf( a1, pm3, q2);
            q3 = fmaf( a0, pm3, q3);
        }
        // new raw state
        const float nw0 = pA0 + pB0, nw1 = pA1 + pB1;
        const float nw2 = pA2 + pB2, nw3 = pA3 + pB3;

        // ---- OFF the critical path: exact normalize for the output ----
        float s = nw0 * nw0 + nw1 * nw1;
        s = fmaf(nw2, nw2, s);
        s = fmaf(nw3, nw3, s);
        s += __shfl_xor_sync(FULLMASK, s, 1);
        s += __shfl_xor_sync(FULLMASK, s, 2);
        s += __shfl_xor_sync(FULLMASK, s, 4);
        s += 1e-12f;
        float rn = rsqrtf(s);
        rn = rn * (1.5f - 0.5f * s * rn * rn);   // one NR step
        const float st0 = nw0 * rn, st1 = nw1 * rn;
        const float st2 = nw2 * rn, st3 = nw3 * rn;

        // projection partials for this lane's 4 columns
        float p0, p1, p2, p3, p4, p5;
        p0 = st0 * wo[0][0]; p1 = st0 * wo[0][1]; p2 = st0 * wo[0][2];
        p3 = st0 * wo[0][3]; p4 = st0 * wo[0][4]; p5 = st0 * wo[0][5];
        p0 = fmaf(st1, wo[1][0], p0); p1 = fmaf(st1, wo[1][1], p1);
        p2 = fmaf(st1, wo[1][2], p2); p3 = fmaf(st1, wo[1][3], p3);
        p4 = fmaf(st1, wo[1][4], p4); p5 = fmaf(st1, wo[1][5], p5);
        p0 = fmaf(st2, wo[2][0], p0); p1 = fmaf(st2, wo[2][1], p1);
        p2 = fmaf(st2, wo[2][2], p2); p3 = fmaf(st2, wo[2][3], p3);
        p4 = fmaf(st2, wo[2][4], p4); p5 = fmaf(st2, wo[2][5], p5);
        p0 = fmaf(st3, wo[3][0], p0); p1 = fmaf(st3, wo[3][1], p1);
        p2 = fmaf(st3, wo[3][2], p2); p3 = fmaf(st3, wo[3][3], p3);
        p4 = fmaf(st3, wo[3][4], p4); p5 = fmaf(st3, wo[3][5], p5);
        // 8-lane (within-head) butterfly reduce
#pragma unroll
        for (int o = 1; o < 8; o <<= 1) {
            p0 += __shfl_xor_sync(FULLMASK, p0, o);
            p1 += __shfl_xor_sync(FULLMASK, p1, o);
            p2 += __shfl_xor_sync(FULLMASK, p2, o);
            p3 += __shfl_xor_sync(FULLMASK, p3, o);
            p4 += __shfl_xor_sync(FULLMASK, p4, o);
            p5 += __shfl_xor_sync(FULLMASK, p5, o);
        }
        const float pv = (g == 0) ? p0 : (g == 1) ? p1 : (g == 2) ? p2
                       : (g == 3) ? p3 : (g == 4) ? p4 : p5;
        if (g < 6) *pw = pv;
        pw += 96;

        // rotate state / scales / inputs
        w0 = nw0; w1 = nw1; w2 = nw2; w3 = nw3;
        rnA = rnB; rnB = rn;
        xp = xn;
#pragma unroll
        for (int d = 0; d < Dd; ++d) cx[d] = nx[d];
    }
}

// ---------------------------------------------------------------------------
// Phase 2: combine — y[row,d] = x[row,d] + b_out[d] + sum_{16 heads} part
// Partials contiguous per (row,d): 4x LDG.128.
// ---------------------------------------------------------------------------
__global__ void __launch_bounds__(256) combine_kernel(
    const float* __restrict__ x,
    const float* __restrict__ b_out,
    float* __restrict__ y)
{
    const int e   = blockIdx.x * blockDim.x + threadIdx.x;  // 0..393215
    const int row = e / 6;              // chain*256 + t
    const int d   = e - row * 6;

    const float4* pp = (const float4*)(g_part + (size_t)row * 96 + d * 16);
    float4 v0 = __ldg(pp + 0);
    float4 v1 = __ldg(pp + 1);
    float4 v2 = __ldg(pp + 2);
    float4 v3 = __ldg(pp + 3);
    float acc = __ldg(b_out + d)
              + ((v0.x + v0.y) + (v0.z + v0.w))
              + ((v1.x + v1.y) + (v1.z + v1.w))
              + ((v2.x + v2.y) + (v2.z + v2.w))
              + ((v3.x + v3.y) + (v3.z + v3.w));

    const int c = row >> 8;
    const int t = row & (Ss - 1);
    const int b = c >> 4;
    const int n = c & (Nn - 1);
    const size_t off = (((size_t)b * Ss + t) * Nn + n) * Dd + d;
    y[off] = __ldg(x + off) + acc;
}

extern "C" void kernel_launch(void* const* d_in, const int* in_sizes, int n_in,
                              void* d_out, int out_size) {
    const float* x     = (const float*)d_in[0];
    const float* W_in  = (const float*)d_in[1];
    const float* b_in  = (const float*)d_in[2];
    const float* W_out = (const float*)d_in[3];
    const float* b_out = (const float*)d_in[4];
    float* y = (float*)d_out;

    // Phase 1: 1024 warps (8/block), smem-based GP exchange
    rotor_rnn_kernel<<<128, 256>>>(x, W_in, b_in, W_out);
    // Phase 2: combine (65536 rows x 6)
    combine_kernel<<<1536, 256>>>(x, b_out, y);
}

// round 8
// speedup vs baseline: 1.2950x; 1.0785x over previous
#include <cuda_runtime.h>

#define FULLMASK 0xffffffffu

// Problem dims (fixed by the dataset)
#define Bb 16
#define Ss 256
#define Nn 16
#define Dd 6
#define Hh 16
#define CHAINS (Bb * Nn)   // 256
#define HW16 (Hh * 16)     // 256 labels per half

// Per-(row) projection partials, layout [row][d*16 + head] = 25 MB
__device__ float g_part[(size_t)CHAINS * Ss * 96];

// Duality-transformed weights: [half][D][H*16], [half][H*16], [half][H*16][D]
__device__ float g_win [2][Dd][HW16];
__device__ float g_bin [2][HW16];
__device__ float g_wout[2][HW16][Dd];

// ---- Clifford sign machinery (5-bit blade masks, matches reference Cayley) ----
__host__ __device__ constexpr unsigned popc5(unsigned v) {
    v &= 31u;
    return (v & 1u) + ((v >> 1) & 1u) + ((v >> 2) & 1u) + ((v >> 3) & 1u) + ((v >> 4) & 1u);
}
__host__ __device__ constexpr int csn(unsigned a, unsigned b) {
    a >>= 1; int s = 0;
    while (a) { s += (int)popc5(a & b); a >>= 1; }
    return s & 1;
}
// lift 4-bit even-subalgebra label -> 5-bit even blade mask
__host__ __device__ constexpr unsigned lift4(unsigned L) {
    L &= 15u;
    unsigned p = (L ^ (L >> 1) ^ (L >> 2) ^ (L >> 3)) & 1u;
    return L | (p << 4);
}
// compile-time residual sign table: bit(m*16+s*4+jr) = csn(lift(m*4+s), lift(jr))
__host__ __device__ constexpr unsigned long long buildCT() {
    unsigned long long t = 0;
    for (unsigned m = 0; m < 4; ++m)
        for (unsigned s = 0; s < 4; ++s)
            for (unsigned jr = 0; jr < 4; ++jr)
                if (csn(lift4((m << 2) | s), lift4(jr)))
                    t |= 1ull << (m * 16 + s * 4 + jr);
    return t;
}
#define CTBITS 0ull
static constexpr unsigned long long CT_TABLE = buildCT();
#define CT(m, s, jr) (int)((CT_TABLE >> ((m) * 16 + (s) * 4 + (jr))) & 1ull)

// ---------------------------------------------------------------------------
// Prep: build duality-transformed weights.
//   ualpha_E = u_E + s31(E^31) * u_{E^31}   (beta: minus)
//   Wout~a[E] = Wout[E] + s31(E) * Wout[E^31]  (beta: minus)
// ---------------------------------------------------------------------------
__global__ void prep_kernel(const float* __restrict__ W_in,
                            const float* __restrict__ b_in,
                            const float* __restrict__ W_out)
{
    const int i = blockIdx.x * blockDim.x + threadIdx.x;   // 0..255
    if (i >= HW16) return;
    const int h = i >> 4, L = i & 15;
    const unsigned E  = lift4((unsigned)L);
    const unsigned Ed = E ^ 31u;
    const float sIn  = csn(31u, Ed) ? -1.0f : 1.0f;
    const float sOut = csn(31u, E)  ? -1.0f : 1.0f;
    const int colE = h * 32 + (int)E;
    const int colD = h * 32 + (int)Ed;
#pragma unroll
    for (int d = 0; d < Dd; ++d) {
        const float we = W_in[d * 512 + colE], wd = W_in[d * 512 + colD];
        g_win[0][d][i] = we + sIn * wd;
        g_win[1][d][i] = we - sIn * wd;
        const float oe = W_out[colE * Dd + d], od = W_out[colD * Dd + d];
        g_wout[0][i][d] = oe + sOut * od;
        g_wout[1][i][d] = oe - sOut * od;
    }
    const float be = b_in[colE], bd = b_in[colD];
    g_bin[0][i] = be + sIn * bd;
    g_bin[1][i] = be - sIn * bd;
}

// ---------------------------------------------------------------------------
// Phase 1: rotor recurrence in split (ideal) coordinates + fused projection.
// Head = 8 lanes: lanes [hb..hb+3] carry alpha (16 coords, 4/lane),
// [hb+4..hb+7] carry beta. 4 heads/warp, 1024 warps.
// Carrier is unnormalized (stale-rn scale); exact normalize for output only.
// ---------------------------------------------------------------------------
__global__ void __launch_bounds__(256) rotor_rnn_kernel(
    const float* __restrict__ x)      // [B,S,N,D]
{
    // [buf][warp][0=w,1=dl][lane]
    __shared__ float4 sbuf[2][8][2][32];

    const int gw   = (blockIdx.x * blockDim.x + threadIdx.x) >> 5;  // 0..1023
    const int wid  = (threadIdx.x >> 5) & 7;
    const int lane = threadIdx.x & 31;
    const int c  = gw >> 2;             // chain 0..255
    const int hq = gw & 3;              // head quad
    const int hw   = lane >> 3;         // head within quad
    const int half = (lane >> 2) & 1;   // 0 = alpha, 1 = beta
    const int g2   = lane & 3;          // label group (labels g2*4..g2*4+3)
    const int h  = hq * 4 + hw;
    const int b  = c >> 4;
    const int n  = c & (Nn - 1);
    const int col = h * 16 + g2 * 4;
    const int dlbase = lane & 28;       // own half's group-0 lane

    // per-lane weights (transformed)
    float wi[4][Dd], bi[4], wo[4][Dd];
#pragma unroll
    for (int r = 0; r < 4; ++r) {
#pragma unroll
        for (int d = 0; d < Dd; ++d) {
            wi[r][d] = g_win[half][d][col + r];
            wo[r][d] = g_wout[half][col + r][d];
        }
        bi[r] = g_bin[half][col + r];
    }

    // runtime sign masks: smC[m][s] = csn(lift(m*4+s), lift((g2^m)<<2)) << 31
    unsigned smC[4][4];
#pragma unroll
    for (int m = 0; m < 4; ++m) {
        const unsigned jhi = lift4((unsigned)(((g2 ^ m) & 3) << 2));
#pragma unroll
        for (int s = 0; s < 4; ++s)
            smC[m][s] = (unsigned)csn(lift4((unsigned)((m << 2) | s)), jhi) << 31;
    }

    // init: psi0 = scalar 1 -> alpha = beta = 0.5 at label 0  (|psi0| = 1)
    float w0 = (g2 == 0) ? 0.5f : 0.0f, w1 = 0.f, w2 = 0.f, w3 = 0.f;
    float rnA = 1.0f, rnB = 1.0f;

    const float* xp = x + ((size_t)(b * Ss) * Nn + n) * Dd;
    float* pw = g_part + ((size_t)c * Ss) * 96 + (lane & 7) * 16 + h;

    float cx[Dd];
#pragma unroll
    for (int d = 0; d < Dd; ++d) cx[d] = __ldg(xp + d);

    for (int t = 0; t < Ss; ++t) {
        const int buf = t & 1;

        // prefetch next x
        const float* xn = xp + Nn * Dd;
        const bool more = (t + 1 < Ss);
        float nx[Dd];
#pragma unroll
        for (int d = 0; d < Dd; ++d) nx[d] = more ? __ldg(xn + d) : 0.0f;

        // u-half = x @ W~ + b~ ; +1 at label 0 ; scaled by stale rn
        float dl0, dl1, dl2, dl3;
        {
            float a0 = bi[0], a1 = bi[1], a2 = bi[2], a3 = bi[3];
#pragma unroll
            for (int d = 0; d < Dd; ++d) {
                a0 = fmaf(wi[0][d], cx[d], a0);
                a1 = fmaf(wi[1][d], cx[d], a1);
                a2 = fmaf(wi[2][d], cx[d], a2);
                a3 = fmaf(wi[3][d], cx[d], a3);
            }
            if (g2 == 0) a0 += 1.0f;
            dl0 = a0 * rnA; dl1 = a1 * rnA; dl2 = a2 * rnA; dl3 = a3 * rnA;
        }

        // publish state + dl (double-buffered, one syncwarp per step)
        sbuf[buf][wid][0][lane] = make_float4(w0, w1, w2, w3);
        sbuf[buf][wid][1][lane] = make_float4(dl0, dl1, dl2, dl3);
        __syncwarp();

        // 16-dim signed XOR-convolution (per half), 4 masks
        float pA0 = 0.f, pA1 = 0.f, pA2 = 0.f, pA3 = 0.f;
        float pB0 = 0.f, pB1 = 0.f, pB2 = 0.f, pB3 = 0.f;
#pragma unroll
        for (int m = 0; m < 4; ++m) {
            float pm0, pm1, pm2, pm3;
            if (m == 0) { pm0 = w0; pm1 = w1; pm2 = w2; pm3 = w3; }
            else {
                const float4 wv = sbuf[buf][wid][0][lane ^ m];
                pm0 = wv.x; pm1 = wv.y; pm2 = wv.z; pm3 = wv.w;
            }
            const float4 dv = sbuf[buf][wid][1][dlbase | m];
            const float as0 = __uint_as_float(__float_as_uint(dv.x) ^ smC[m][0]);
            const float as1 = __uint_as_float(__float_as_uint(dv.y) ^ smC[m][1]);
            const float as2 = __uint_as_float(__float_as_uint(dv.z) ^ smC[m][2]);
            const float as3 = __uint_as_float(__float_as_uint(dv.w) ^ smC[m][3]);

            float& q0 = (m & 1) ? pB0 : pA0;
            float& q1 = (m & 1) ? pB1 : pA1;
            float& q2 = (m & 1) ? pB2 : pA2;
            float& q3 = (m & 1) ? pB3 : pA3;

            // s = 0: jr = kr
            q0 = fmaf(CT(m,0,0) ? -as0 : as0, pm0, q0);
            q1 = fmaf(CT(m,0,1) ? -as0 : as0, pm1, q1);
            q2 = fmaf(CT(m,0,2) ? -as0 : as0, pm2, q2);
            q3 = fmaf(CT(m,0,3) ? -as0 : as0, pm3, q3);
            // s = 1: jr = 1^kr
            q0 = fmaf(CT(m,1,1) ? -as1 : as1, pm1, q0);
            q1 = fmaf(CT(m,1,0) ? -as1 : as1, pm0, q1);
            q2 = fmaf(CT(m,1,3) ? -as1 : as1, pm3, q2);
            q3 = fmaf(CT(m,1,2) ? -as1 : as1, pm2, q3);
            // s = 2: jr = 2^kr
            q0 = fmaf(CT(m,2,2) ? -as2 : as2, pm2, q0);
            q1 = fmaf(CT(m,2,3) ? -as2 : as2, pm3, q1);
            q2 = fmaf(CT(m,2,0) ? -as2 : as2, pm0, q2);
            q3 = fmaf(CT(m,2,1) ? -as2 : as2, pm1, q3);
            // s = 3: jr = 3^kr
            q0 = fmaf(CT(m,3,3) ? -as3 : as3, pm3, q0);
            q1 = fmaf(CT(m,3,2) ? -as3 : as3, pm2, q1);
            q2 = fmaf(CT(m,3,1) ? -as3 : as3, pm1, q2);
            q3 = fmaf(CT(m,3,0) ? -as3 : as3, pm0, q3);
        }
        const float nw0 = pA0 + pB0, nw1 = pA1 + pB1;
        const float nw2 = pA2 + pB2, nw3 = pA3 + pB3;

        // ---- off the critical path: exact normalize for output ----
        // |psi|^2 = 2 * (|alpha|^2 + |beta|^2); 8-lane reduce spans both halves
        float s = nw0 * nw0 + nw1 * nw1;
        s = fmaf(nw2, nw2, s);
        s = fmaf(nw3, nw3, s);
        s += __shfl_xor_sync(FULLMASK, s, 1);
        s += __shfl_xor_sync(FULLMASK, s, 2);
        s += __shfl_xor_sync(FULLMASK, s, 4);
        s = s + s + 1e-12f;
        float rn = rsqrtf(s);
        rn = rn * (1.5f - 0.5f * s * rn * rn);   // one NR step
        const float st0 = nw0 * rn, st1 = nw1 * rn;
        const float st2 = nw2 * rn, st3 = nw3 * rn;

        // projection partials (half-appropriate W~out), 8-lane reduce sums halves
        float p0, p1, p2, p3, p4, p5;
        p0 = st0 * wo[0][0]; p1 = st0 * wo[0][1]; p2 = st0 * wo[0][2];
        p3 = st0 * wo[0][3]; p4 = st0 * wo[0][4]; p5 = st0 * wo[0][5];
        p0 = fmaf(st1, wo[1][0], p0); p1 = fmaf(st1, wo[1][1], p1);
        p2 = fmaf(st1, wo[1][2], p2); p3 = fmaf(st1, wo[1][3], p3);
        p4 = fmaf(st1, wo[1][4], p4); p5 = fmaf(st1, wo[1][5], p5);
        p0 = fmaf(st2, wo[2][0], p0); p1 = fmaf(st2, wo[2][1], p1);
        p2 = fmaf(st2, wo[2][2], p2); p3 = fmaf(st2, wo[2][3], p3);
        p4 = fmaf(st2, wo[2][4], p4); p5 = fmaf(st2, wo[2][5], p5);
        p0 = fmaf(st3, wo[3][0], p0); p1 = fmaf(st3, wo[3][1], p1);
        p2 = fmaf(st3, wo[3][2], p2); p3 = fmaf(st3, wo[3][3], p3);
        p4 = fmaf(st3, wo[3][4], p4); p5 = fmaf(st3, wo[3][5], p5);
#pragma unroll
        for (int o = 1; o < 8; o <<= 1) {
            p0 += __shfl_xor_sync(FULLMASK, p0, o);
            p1 += __shfl_xor_sync(FULLMASK, p1, o);
            p2 += __shfl_xor_sync(FULLMASK, p2, o);
            p3 += __shfl_xor_sync(FULLMASK, p3, o);
            p4 += __shfl_xor_sync(FULLMASK, p4, o);
            p5 += __shfl_xor_sync(FULLMASK, p5, o);
        }
        const int gg = lane & 7;
        const float pv = (gg == 0) ? p0 : (gg == 1) ? p1 : (gg == 2) ? p2
                       : (gg == 3) ? p3 : (gg == 4) ? p4 : p5;
        if (gg < 6) *pw = pv;
        pw += 96;

        // rotate state
        w0 = nw0; w1 = nw1; w2 = nw2; w3 = nw3;
        rnA = rnB; rnB = rn;
        xp = xn;
#pragma unroll
        for (int d = 0; d < Dd; ++d) cx[d] = nx[d];
    }
}

// ---------------------------------------------------------------------------
// Phase 2: combine — y[row,d] = x[row,d] + b_out[d] + sum_{16 heads} part
// ---------------------------------------------------------------------------
__global__ void __launch_bounds__(256) combine_kernel(
    const float* __restrict__ x,
    const float* __restrict__ b_out,
    float* __restrict__ y)
{
    const int e   = blockIdx.x * blockDim.x + threadIdx.x;  // 0..393215
    const int row = e / 6;              // chain*256 + t
    const int d   = e - row * 6;

    const float4* pp = (const float4*)(g_part + (size_t)row * 96 + d * 16);
    float4 v0 = __ldg(pp + 0);
    float4 v1 = __ldg(pp + 1);
    float4 v2 = __ldg(pp + 2);
    float4 v3 = __ldg(pp + 3);
    float acc = __ldg(b_out + d)
              + ((v0.x + v0.y) + (v0.z + v0.w))
              + ((v1.x + v1.y) + (v1.z + v1.w))
              + ((v2.x + v2.y) + (v2.z + v2.w))
              + ((v3.x + v3.y) + (v3.z + v3.w));

    const int c = row >> 8;
    const int t = row & (Ss - 1);
    const int b = c >> 4;
    const int n = c & (Nn - 1);
    const size_t off = (((size_t)b * Ss + t) * Nn + n) * Dd + d;
    y[off] = __ldg(x + off) + acc;
}

extern "C" void kernel_launch(void* const* d_in, const int* in_sizes, int n_in,
                              void* d_out, int out_size) {
    const float* x     = (const float*)d_in[0];
    const float* W_in  = (const float*)d_in[1];
    const float* b_in  = (const float*)d_in[2];
    const float* W_out = (const float*)d_in[3];
    const float* b_out = (const float*)d_in[4];
    float* y = (float*)d_out;

    // Prep: duality-transformed weights (256 threads, ~microseconds)
    prep_kernel<<<1, 256>>>(W_in, b_in, W_out);
    // Phase 1: 1024 warps, split-ideal recurrence + fused projection
    rotor_rnn_kernel<<<128, 256>>>(x);
    // Phase 2: combine
    combine_kernel<<<1536, 256>>>(x, b_out, y);
}